// round 2
// baseline (speedup 1.0000x reference)
#include <cuda_runtime.h>

// ---------------------------------------------------------------------------
// Sparse 3-layer conv net (ME-style gather-GEMM-scatter) on GB300.
// Strategy: invert (in_idx, out_idx) pair lists per kernel offset into dense
// per-output gather tables (valid since out_idx is unique within an offset),
// then each layer is gather + register accumulate + one store. No atomics.
// ---------------------------------------------------------------------------

#define N1_MAX 300001     // fine points + 1 dummy row for pad writes
#define N2_MAX 262145     // max coarse voxels (64^3) + 1 dummy row

// Scratch (device globals: allocation-free per harness rules)
__device__ int   g_tab1[N1_MAX * 27];
__device__ int   g_tab2[N2_MAX * 8];
__device__ int   g_tab3[N2_MAX * 27];
__device__ float g_h1[(N1_MAX - 1) * 64];
__device__ float g_h2[(N2_MAX - 1) * 64];

// ---------------- table fill (-1 sentinel) ----------------
__global__ void fill_kernel(int which, int n) {
    int* p = (which == 0) ? g_tab1 : (which == 1) ? g_tab2 : g_tab3;
    int i = blockIdx.x * blockDim.x + threadIdx.x;
    int stride = gridDim.x * blockDim.x;
    for (; i < n; i += stride) p[i] = -1;
}

// ---------------- table build: tab[out*K + k] = in ----------------
// Pad entries have out == n_out (dummy row) and in == 0; concurrent identical
// writes to the dummy row are benign, and the dummy row is never read.
__global__ void build_kernel(const int* __restrict__ m_in,
                             const int* __restrict__ m_out,
                             int which, int K, int L) {
    int* tab = (which == 0) ? g_tab1 : (which == 1) ? g_tab2 : g_tab3;
    int total = K * L;
    int i = blockIdx.x * blockDim.x + threadIdx.x;
    int stride = gridDim.x * blockDim.x;
    for (; i < total; i += stride) {
        int k = i / L;
        int o = m_out[i];
        tab[o * K + k] = m_in[i];
    }
}

// ---------------- layer 1: 27 offsets, 8 -> 64, ReLU ----------------
// Warp per output row. W1 (27*8*64 = 13824 f32 = 55296 B) in dynamic smem.
// Each lane owns channels (lane, lane+32). x row broadcast via shuffles.
__global__ void __launch_bounds__(256) layer1_kernel(
    const float* __restrict__ feats, const float* __restrict__ W1,
    const float* __restrict__ b1, int n1) {
    extern __shared__ float sW1[];           // 13824 floats
    for (int i = threadIdx.x; i < 27 * 512; i += 256) sW1[i] = W1[i];
    __syncthreads();

    int lane = threadIdx.x & 31;
    int gw = (blockIdx.x * 256 + threadIdx.x) >> 5;
    int nw = (gridDim.x * 256) >> 5;
    float bias0 = b1[lane], bias1 = b1[lane + 32];

    for (int o = gw; o < n1; o += nw) {
        float a0 = bias0, a1 = bias1;
        const int* t = g_tab1 + o * 27;
        for (int k = 0; k < 27; k++) {
            int idx = t[k];                  // warp-uniform
            if (idx < 0) continue;
            float xf = 0.f;
            if (lane < 8) xf = feats[idx * 8 + lane];
            const float* w = sW1 + k * 512 + lane;
            #pragma unroll
            for (int f = 0; f < 8; f++) {
                float v = __shfl_sync(0xffffffffu, xf, f);
                a0 = fmaf(v, w[f * 64], a0);
                a1 = fmaf(v, w[f * 64 + 32], a1);
            }
        }
        g_h1[o * 64 + lane]      = fmaxf(a0, 0.f);
        g_h1[o * 64 + lane + 32] = fmaxf(a1, 0.f);
    }
}

// ---------------- layer 2: 8 offsets, 64 -> 64, ReLU ----------------
// Warp per output row. W2 (8*64*64 = 32768 f32 = 128 KB) in dynamic smem,
// x row staged per-warp in smem (broadcast reads, conflict-free weight reads).
__global__ void __launch_bounds__(512) layer2_kernel(
    const float* __restrict__ W2, const float* __restrict__ b2, int n2) {
    extern __shared__ float sm2[];
    float* sW = sm2;                          // 32768 floats
    float* sX = sm2 + 32768;                  // 16 warps * 64 floats
    for (int i = threadIdx.x; i < 32768; i += 512) sW[i] = W2[i];
    __syncthreads();

    int lane = threadIdx.x & 31;
    int warp = threadIdx.x >> 5;
    float* xw = sX + warp * 64;
    int gw = (blockIdx.x * 512 + threadIdx.x) >> 5;
    int nw = (gridDim.x * 512) >> 5;
    float bias0 = b2[lane], bias1 = b2[lane + 32];

    for (int o = gw; o < n2; o += nw) {
        float a0 = bias0, a1 = bias1;
        const int* t = g_tab2 + o * 8;
        for (int k = 0; k < 8; k++) {
            int idx = t[k];                   // warp-uniform
            if (idx < 0) continue;
            xw[lane]      = g_h1[idx * 64 + lane];
            xw[lane + 32] = g_h1[idx * 64 + lane + 32];
            __syncwarp();
            const float* w = sW + k * 4096 + lane;
            #pragma unroll
            for (int f = 0; f < 64; f++) {
                float v = xw[f];
                a0 = fmaf(v, w[f * 64], a0);
                a1 = fmaf(v, w[f * 64 + 32], a1);
            }
            __syncwarp();
        }
        g_h2[o * 64 + lane]      = fmaxf(a0, 0.f);
        g_h2[o * 64 + lane + 32] = fmaxf(a1, 0.f);
    }
}

// ---------------- layer 3: 27 offsets, 64 -> 8, no activation ----------------
// Warp per output row. W3 (27*64*8 = 13824 f32) in smem. Lane = (fg, c) with
// c = lane&7, fg = lane>>3. Weight reads fully coalesced: w[r*32 + lane]
// covers element e = r*32+lane => f = e>>3 = 4r+fg, c = e&7. Butterfly
// reduction over the 4 f-groups; lanes 0..7 write the 8 output channels.
__global__ void __launch_bounds__(256) layer3_kernel(
    const float* __restrict__ W3, const float* __restrict__ b3,
    float* __restrict__ out, int n2) {
    extern __shared__ float sm3[];
    float* sW = sm3;                          // 13824 floats
    float* sX = sm3 + 13824;                  // 8 warps * 64 floats
    for (int i = threadIdx.x; i < 13824; i += 256) sW[i] = W3[i];
    __syncthreads();

    int lane = threadIdx.x & 31;
    int warp = threadIdx.x >> 5;
    int fg = lane >> 3;                       // 0..3
    float* xw = sX + warp * 64;
    int gw = (blockIdx.x * 256 + threadIdx.x) >> 5;
    int nw = (gridDim.x * 256) >> 5;

    for (int o = gw; o < n2; o += nw) {
        float a = 0.f;
        const int* t = g_tab3 + o * 27;
        for (int k = 0; k < 27; k++) {
            int idx = t[k];                   // warp-uniform
            if (idx < 0) continue;
            xw[lane]      = g_h2[idx * 64 + lane];
            xw[lane + 32] = g_h2[idx * 64 + lane + 32];
            __syncwarp();
            const float* w = sW + k * 512;
            #pragma unroll
            for (int r = 0; r < 16; r++) {
                // lane reads w element e=r*32+lane -> (f=4r+fg, c=lane&7)
                a = fmaf(w[r * 32 + lane], xw[4 * r + fg], a);
            }
            __syncwarp();
        }
        // sum over the 4 f-groups (lane bits 3,4)
        a += __shfl_xor_sync(0xffffffffu, a, 16);
        a += __shfl_xor_sync(0xffffffffu, a, 8);
        if (lane < 8) out[o * 8 + lane] = a + b3[lane];
    }
}

// ---------------------------------------------------------------------------
extern "C" void kernel_launch(void* const* d_in, const int* in_sizes, int n_in,
                              void* d_out, int out_size) {
    const float* feats = (const float*)d_in[0];
    const float* W1    = (const float*)d_in[1];
    const float* b1    = (const float*)d_in[2];
    const float* W2    = (const float*)d_in[3];
    const float* b2    = (const float*)d_in[4];
    const float* W3    = (const float*)d_in[5];
    const float* b3    = (const float*)d_in[6];
    const int* map1_in  = (const int*)d_in[7];
    const int* map1_out = (const int*)d_in[8];
    const int* map2_in  = (const int*)d_in[9];
    const int* map2_out = (const int*)d_in[10];
    const int* map3_in  = (const int*)d_in[11];
    const int* map3_out = (const int*)d_in[12];
    float* out = (float*)d_out;

    int n1 = in_sizes[0] / 8;
    int n2 = out_size / 8;
    int L1 = in_sizes[7] / 27;
    int L2 = in_sizes[9] / 8;
    int L3 = in_sizes[11] / 27;

    // dynamic smem opt-in (>48KB for layer1/layer2/layer3)
    cudaFuncSetAttribute(layer1_kernel, cudaFuncAttributeMaxDynamicSharedMemorySize, 27 * 512 * 4);
    cudaFuncSetAttribute(layer2_kernel, cudaFuncAttributeMaxDynamicSharedMemorySize, (32768 + 16 * 64) * 4);
    cudaFuncSetAttribute(layer3_kernel, cudaFuncAttributeMaxDynamicSharedMemorySize, (13824 + 8 * 64) * 4);

    // 1) fill gather tables with -1 (only the readable n_out*K region)
    fill_kernel<<<2048, 256>>>(0, n1 * 27);
    fill_kernel<<<2048, 256>>>(1, n2 * 8);
    fill_kernel<<<2048, 256>>>(2, n2 * 27);

    // 2) invert pair lists into gather tables
    build_kernel<<<2048, 256>>>(map1_in, map1_out, 0, 27, L1);
    build_kernel<<<2048, 256>>>(map2_in, map2_out, 1, 8, L2);
    build_kernel<<<2048, 256>>>(map3_in, map3_out, 2, 27, L3);

    // 3) layers
    layer1_kernel<<<592, 256, 27 * 512 * 4>>>(feats, W1, b1, n1);
    layer2_kernel<<<148, 512, (32768 + 16 * 64) * 4>>>(W2, b2, n2);
    layer3_kernel<<<444, 256, (13824 + 8 * 64) * 4>>>(W3, b3, out, n2);
}

// round 6
// speedup vs baseline: 1.2668x; 1.2668x over previous
#include <cuda_runtime.h>

// ---------------------------------------------------------------------------
// Sparse 3-layer conv net (ME-style). Round 3:
//  - gather tables (no atomics) built with vectorized fill + div-free build
//  - layer1: 2 rows/warp (weight-LDS reuse)
//  - layer2: warp-per-row register accumulation (unchanged)
//  - layer3: dense GEMM S3 = H2 @ W3r with packed fma.rn.f32x2, then
//            gather-sum epilogue (out[o][c] = b3[c] + sum_k S3[tab3[o][k]][k*8+c])
// ---------------------------------------------------------------------------

#define N1_MAX 300001     // fine points + 1 dummy row
#define N2_MAX 262145     // max coarse voxels (64^3) + 1 dummy row

// Scratch (device globals; allocation-free per harness rules)
__device__ int4  g_tab1_v[(N1_MAX * 27 + 3) / 4];
__device__ int4  g_tab2_v[(N2_MAX * 8 + 3) / 4];
__device__ int4  g_tab3_v[(N2_MAX * 27 + 3) / 4];
__device__ float g_h1[(N1_MAX - 1) * 64];
__device__ float g_h2[(N2_MAX - 1) * 64];
__device__ float g_W3r[64 * 216];                 // W3 repacked: [f][k*8+c]
__device__ float g_S3[(N2_MAX - 1) * 216];        // per-input transforms, layer3

__device__ __forceinline__ unsigned long long pack2(float a, float b) {
    unsigned long long r;
    asm("mov.b64 %0, {%1, %2};" : "=l"(r)
        : "r"(__float_as_uint(a)), "r"(__float_as_uint(b)));
    return r;
}
__device__ __forceinline__ unsigned long long dup2(float a) {
    unsigned long long r;
    asm("mov.b64 %0, {%1, %1};" : "=l"(r) : "r"(__float_as_uint(a)));
    return r;
}

// ---------------- table fill: vectorized -1 ----------------
__global__ void fill_kernel(int which, int n4) {
    int4* p = (which == 0) ? g_tab1_v : (which == 1) ? g_tab2_v : g_tab3_v;
    const int4 v = make_int4(-1, -1, -1, -1);
    int i = blockIdx.x * blockDim.x + threadIdx.x;
    int stride = gridDim.x * blockDim.x;
    for (; i < n4; i += stride) p[i] = v;
}

// ---------------- table build: tab[out*K + k] = in (k = blockIdx.y) ----------
__global__ void build_kernel(const int* __restrict__ m_in,
                             const int* __restrict__ m_out,
                             int which, int K, int L) {
    int* tab = (which == 0) ? (int*)g_tab1_v : (which == 1) ? (int*)g_tab2_v
                                                            : (int*)g_tab3_v;
    int k = blockIdx.y;
    const int* mi = m_in + k * L;
    const int* mo = m_out + k * L;
    int i = blockIdx.x * blockDim.x + threadIdx.x;
    int stride = gridDim.x * blockDim.x;
    for (; i < L; i += stride) tab[mo[i] * K + k] = mi[i];
}

// ---------------- W3 repack: W3r[f*216 + k*8 + c] = W3[k][f][c] --------------
__global__ void repack_w3_kernel(const float* __restrict__ W3) {
    int i = blockIdx.x * blockDim.x + threadIdx.x;
    if (i < 27 * 512) {
        int k = i >> 9, rem = i & 511, f = rem >> 3, c = rem & 7;
        g_W3r[f * 216 + k * 8 + c] = W3[i];
    }
}

// ---------------- layer 1: 27 offsets, 8 -> 64, ReLU, 2 rows/warp ------------
__global__ void __launch_bounds__(256) layer1_kernel(
    const float* __restrict__ feats, const float* __restrict__ W1,
    const float* __restrict__ b1, int n1) {
    extern __shared__ float sW1[];           // 13824 floats
    for (int i = threadIdx.x; i < 27 * 512; i += 256) sW1[i] = W1[i];
    __syncthreads();

    const int* tab1 = (const int*)g_tab1_v;
    int lane = threadIdx.x & 31;
    int gw = (blockIdx.x * 256 + threadIdx.x) >> 5;
    int nw = (gridDim.x * 256) >> 5;
    float bias0 = b1[lane], bias1 = b1[lane + 32];
    int npairs = (n1 + 1) >> 1;

    for (int p = gw; p < npairs; p += nw) {
        int o0 = 2 * p, o1 = 2 * p + 1;
        bool r1v = (o1 < n1);
        const int* t0 = tab1 + o0 * 27;
        const int* t1 = tab1 + o1 * 27;
        float a00 = bias0, a01 = bias1, a10 = bias0, a11 = bias1;
        for (int k = 0; k < 27; k++) {
            int i0 = t0[k];
            int i1 = r1v ? t1[k] : -1;
            if (i0 < 0 && i1 < 0) continue;
            float xf = 0.f;
            if (lane < 8) { if (i0 >= 0) xf = feats[i0 * 8 + lane]; }
            else if (lane < 16) { if (i1 >= 0) xf = feats[i1 * 8 + lane - 8]; }
            const float* w = sW1 + k * 512 + lane;
            #pragma unroll
            for (int f = 0; f < 8; f++) {
                float v0 = __shfl_sync(0xffffffffu, xf, f);
                float v1 = __shfl_sync(0xffffffffu, xf, 8 + f);
                float w0 = w[f * 64], w1 = w[f * 64 + 32];
                a00 = fmaf(v0, w0, a00);
                a01 = fmaf(v0, w1, a01);
                a10 = fmaf(v1, w0, a10);
                a11 = fmaf(v1, w1, a11);
            }
        }
        g_h1[o0 * 64 + lane]      = fmaxf(a00, 0.f);
        g_h1[o0 * 64 + lane + 32] = fmaxf(a01, 0.f);
        if (r1v) {
            g_h1[o1 * 64 + lane]      = fmaxf(a10, 0.f);
            g_h1[o1 * 64 + lane + 32] = fmaxf(a11, 0.f);
        }
    }
}

// ---------------- layer 2: 8 offsets, 64 -> 64, ReLU ----------------
__global__ void __launch_bounds__(512) layer2_kernel(
    const float* __restrict__ W2, const float* __restrict__ b2, int n2) {
    extern __shared__ float sm2[];
    float* sW = sm2;                          // 32768 floats
    float* sX = sm2 + 32768;                  // 16 warps * 64 floats
    for (int i = threadIdx.x; i < 32768; i += 512) sW[i] = W2[i];
    __syncthreads();

    const int* tab2 = (const int*)g_tab2_v;
    int lane = threadIdx.x & 31;
    int warp = threadIdx.x >> 5;
    float* xw = sX + warp * 64;
    int gw = (blockIdx.x * 512 + threadIdx.x) >> 5;
    int nw = (gridDim.x * 512) >> 5;
    float bias0 = b2[lane], bias1 = b2[lane + 32];

    for (int o = gw; o < n2; o += nw) {
        float a0 = bias0, a1 = bias1;
        const int* t = tab2 + o * 8;
        for (int k = 0; k < 8; k++) {
            int idx = t[k];                   // warp-uniform
            if (idx < 0) continue;
            xw[lane]      = g_h1[idx * 64 + lane];
            xw[lane + 32] = g_h1[idx * 64 + lane + 32];
            __syncwarp();
            const float* w = sW + k * 4096 + lane;
            #pragma unroll
            for (int f = 0; f < 64; f++) {
                float v = xw[f];
                a0 = fmaf(v, w[f * 64], a0);
                a1 = fmaf(v, w[f * 64 + 32], a1);
            }
            __syncwarp();
        }
        g_h2[o * 64 + lane]      = fmaxf(a0, 0.f);
        g_h2[o * 64 + lane + 32] = fmaxf(a1, 0.f);
    }
}

// ---------------- layer 3 GEMM: S3[n2][216] = H2[n2][64] @ W3r[64][216] ------
// Block: 256 threads = 8 warps; 64 rows/block (8 rows/warp).
// Lane owns cols {lane + 32j, j=0..6} (padded to 224); rows packed in f32x2
// pairs -> 28 fma.rn.f32x2 per k-step per lane (FMA-pipe bound).
__global__ void __launch_bounds__(256) l3gemm_kernel(int n2) {
    extern __shared__ float sm3[];
    float* sW = sm3;                 // 64 * 224
    float* sX = sm3 + 64 * 224;      // 64 * 64

    for (int i = threadIdx.x; i < 64 * 224; i += 256) {
        int k = i / 224, c = i - k * 224;
        sW[i] = (c < 216) ? g_W3r[k * 216 + c] : 0.f;
    }
    int base = blockIdx.x << 6;
    for (int i = threadIdx.x; i < 1024; i += 256) {   // 64 rows * 16 float4
        int r = i >> 4, q = i & 15;
        int row = base + r;
        float4 v = make_float4(0.f, 0.f, 0.f, 0.f);
        if (row < n2) v = ((const float4*)g_h2)[row * 16 + q];
        ((float4*)sX)[i] = v;
    }
    __syncthreads();

    int lane = threadIdx.x & 31, warp = threadIdx.x >> 5;
    const float* xw = sX + warp * 512;        // 8 rows of 64

    unsigned long long acc[4][7];
    #pragma unroll
    for (int p = 0; p < 4; p++)
        #pragma unroll
        for (int j = 0; j < 7; j++) acc[p][j] = 0ull;

    #pragma unroll 4
    for (int k = 0; k < 64; k++) {
        unsigned long long xp[4];
        #pragma unroll
        for (int p = 0; p < 4; p++)
            xp[p] = pack2(xw[(2 * p) * 64 + k], xw[(2 * p + 1) * 64 + k]);
        const float* wr = sW + k * 224 + lane;
        #pragma unroll
        for (int j = 0; j < 7; j++) {
            unsigned long long ww = dup2(wr[j * 32]);
            #pragma unroll
            for (int p = 0; p < 4; p++)
                asm("fma.rn.f32x2 %0, %1, %2, %0;"
                    : "+l"(acc[p][j]) : "l"(xp[p]), "l"(ww));
        }
    }

    int rbase = base + warp * 8;
    #pragma unroll
    for (int p = 0; p < 4; p++) {
        int r0 = rbase + 2 * p;
        #pragma unroll
        for (int j = 0; j < 7; j++) {
            int col = (j << 5) + lane;
            if (col < 216) {
                unsigned int lo = (unsigned int)(acc[p][j]);
                unsigned int hi = (unsigned int)(acc[p][j] >> 32);
                if (r0 < n2)     g_S3[r0 * 216 + col]       = __uint_as_float(lo);
                if (r0 + 1 < n2) g_S3[(r0 + 1) * 216 + col] = __uint_as_float(hi);
            }
        }
    }
}

// ---------------- layer 3 gather-sum: out[o][c] = b3[c] + sum_k S3[idx][k*8+c]
__global__ void __launch_bounds__(256) l3gs_kernel(
    const float* __restrict__ b3, float* __restrict__ out, int n2) {
    __shared__ int st[32 * 27];
    const int* tab3 = (const int*)g_tab3_v;
    int base = blockIdx.x << 5;
    for (int i = threadIdx.x; i < 32 * 27; i += 256) {
        int o = base + i / 27;
        st[i] = (o < n2) ? tab3[o * 27 + i % 27] : -1;
    }
    __syncthreads();

    int lane = threadIdx.x & 31, warp = threadIdx.x >> 5;
    int sub = lane >> 3, c = lane & 7;
    int lo = (warp << 2) + sub;               // local output 0..31
    int o = base + lo;
    const int* t = st + lo * 27;
    float acc = 0.f;
    #pragma unroll
    for (int k = 0; k < 27; k++) {
        int idx = t[k];
        float v = 0.f;
        if (idx >= 0) v = g_S3[idx * 216 + (k << 3) + c];
        acc += v;
    }
    if (o < n2) out[(o << 3) + c] = acc + b3[c];
}

// ---------------------------------------------------------------------------
extern "C" void kernel_launch(void* const* d_in, const int* in_sizes, int n_in,
                              void* d_out, int out_size) {
    const float* feats = (const float*)d_in[0];
    const float* W1    = (const float*)d_in[1];
    const float* b1    = (const float*)d_in[2];
    const float* W2    = (const float*)d_in[3];
    const float* b2    = (const float*)d_in[4];
    const float* W3    = (const float*)d_in[5];
    const float* b3    = (const float*)d_in[6];
    const int* map1_in  = (const int*)d_in[7];
    const int* map1_out = (const int*)d_in[8];
    const int* map2_in  = (const int*)d_in[9];
    const int* map2_out = (const int*)d_in[10];
    const int* map3_in  = (const int*)d_in[11];
    const int* map3_out = (const int*)d_in[12];
    float* out = (float*)d_out;

    int n1 = in_sizes[0] / 8;
    int n2 = out_size / 8;
    int L1 = in_sizes[7] / 27;
    int L2 = in_sizes[9] / 8;
    int L3 = in_sizes[11] / 27;

    cudaFuncSetAttribute(layer1_kernel, cudaFuncAttributeMaxDynamicSharedMemorySize, 27 * 512 * 4);
    cudaFuncSetAttribute(layer2_kernel, cudaFuncAttributeMaxDynamicSharedMemorySize, (32768 + 16 * 64) * 4);
    cudaFuncSetAttribute(l3gemm_kernel, cudaFuncAttributeMaxDynamicSharedMemorySize, (64 * 224 + 64 * 64) * 4);

    // 1) fill gather tables with -1 (int4-vectorized)
    fill_kernel<<<1024, 256>>>(0, (n1 * 27 + 3) / 4);
    fill_kernel<<<1024, 256>>>(1, (n2 * 8 + 3) / 4);
    fill_kernel<<<1024, 256>>>(2, (n2 * 27 + 3) / 4);

    // 2) invert pair lists into gather tables (div-free: k = blockIdx.y)
    {
        dim3 g1((unsigned)min((L1 + 255) / 256, 1184), 27);
        dim3 g2((unsigned)min((L2 + 255) / 256, 1184), 8);
        dim3 g3((unsigned)min((L3 + 255) / 256, 1184), 27);
        build_kernel<<<g1, 256>>>(map1_in, map1_out, 0, 27, L1);
        build_kernel<<<g2, 256>>>(map2_in, map2_out, 1, 8, L2);
        build_kernel<<<g3, 256>>>(map3_in, map3_out, 2, 27, L3);
    }

    // 3) W3 repack (independent of layers 1/2)
    repack_w3_kernel<<<54, 256>>>(W3);

    // 4) layers
    layer1_kernel<<<592, 256, 27 * 512 * 4>>>(feats, W1, b1, n1);
    layer2_kernel<<<148, 512, (32768 + 16 * 64) * 4>>>(W2, b2, n2);
    l3gemm_kernel<<<(n2 + 63) / 64, 256, (64 * 224 + 64 * 64) * 4>>>(n2);
    l3gs_kernel<<<(n2 + 31) / 32, 256>>>(b3, out, n2);
}